// round 16
// baseline (speedup 1.0000x reference)
#include <cuda_runtime.h>

// ---------------------------------------------------------------------------
// Multislice gradient step — radix-4 FFT with 16 elements/thread:
// two register stages per phase, one in-shared stage, 2W+2R shared per pass,
// permuted frequency-scratch layout for fully coalesced global access.
// ---------------------------------------------------------------------------

#define NPIX (1024*1024)
#define NZS  16
#define PI_D 3.14159265358979323846
#define KAPF ((float)(2.0*PI_D*6.5))

// -------------------- device scratch ---------------------------------------
__device__ float2 g_T [(size_t)NZS*NPIX];
__device__ float2 g_G [(size_t)NZS*NPIX];
__device__ float2 g_Ua[NPIX];
__device__ float2 g_Ub[NPIX];
__device__ float2 g_Sa[NPIX];   // freq scratch, permuted layout
__device__ float2 g_Sb[NPIX];   // freq scratch, permuted layout

// -------------------- complex helpers --------------------------------------
__device__ __forceinline__ float2 cadd(float2 a, float2 b){ return make_float2(a.x+b.x, a.y+b.y); }
__device__ __forceinline__ float2 csub(float2 a, float2 b){ return make_float2(a.x-b.x, a.y-b.y); }
__device__ __forceinline__ float2 cmul(float2 a, float2 b){ return make_float2(a.x*b.x-a.y*b.y, a.x*b.y+a.y*b.x); }
__device__ __forceinline__ float2 cmulc(float2 a, float2 b){ return make_float2(a.x*b.x+a.y*b.y, a.y*b.x-a.x*b.y); }

// bank swizzle
__device__ __forceinline__ int swz(int a){ return a ^ ((5*(a>>4)) & 15); }

__device__ __forceinline__ int rev4(int v){
    return ((v & 3) << 8) | (((v >> 2) & 3) << 6) | (((v >> 4) & 3) << 4)
         | (((v >> 6) & 3) << 2) | ((v >> 8) & 3);
}
__device__ __forceinline__ int fidx(int k){ return (k < 512) ? k : k - 1024; }

// 256-entry twiddle table exp(-2*pi*i*k/1024), one entry per thread (256 thr)
__device__ __forceinline__ void fill_tw(float2* W, int tid){
    float s, c;
    sincospif(-(float)tid * (1.0f/512.0f), &s, &c);
    W[swz(tid)] = make_float2(c, s);
}

// -------------------- radix-4 butterfly cores -------------------------------
__device__ __forceinline__ void bf_fwd(float2& a0, float2& a1, float2& a2, float2& a3,
                                       float2 w1, float2 w2, float2 w3){
    float2 t0=cadd(a0,a2), t1=csub(a0,a2), t2=cadd(a1,a3), u=csub(a1,a3);
    float2 mi=make_float2(u.y,-u.x);
    a0=cadd(t0,t2); a1=cmul(cadd(t1,mi),w1); a2=cmul(csub(t0,t2),w2); a3=cmul(csub(t1,mi),w3);
}
__device__ __forceinline__ void bf_fwd_nw(float2& a0, float2& a1, float2& a2, float2& a3){
    float2 t0=cadd(a0,a2), t1=csub(a0,a2), t2=cadd(a1,a3), u=csub(a1,a3);
    float2 mi=make_float2(u.y,-u.x);
    a0=cadd(t0,t2); a1=cadd(t1,mi); a2=csub(t0,t2); a3=csub(t1,mi);
}
__device__ __forceinline__ void bf_inv(float2& a0, float2& a1, float2& a2, float2& a3,
                                       float2 w1, float2 w2, float2 w3){
    float2 c1=cmulc(a1,w1), c2=cmulc(a2,w2), c3=cmulc(a3,w3);
    float2 t0=cadd(a0,c2), t1=csub(a0,c2), t2=cadd(c1,c3), u=csub(c1,c3);
    float2 pi=make_float2(-u.y,u.x);
    a0=cadd(t0,t2); a1=cadd(t1,pi); a2=csub(t0,t2); a3=csub(t1,pi);
}
__device__ __forceinline__ void bf_inv_nw(float2& a0, float2& a1, float2& a2, float2& a3){
    float2 t0=cadd(a0,a2), t1=csub(a0,a2), t2=cadd(a1,a3), u=csub(a1,a3);
    float2 pi=make_float2(-u.y,u.x);
    a0=cadd(t0,t2); a1=cadd(t1,pi); a2=csub(t0,t2); a3=csub(t1,pi);
}

// -------------------- register phases ---------------------------------------
// Phase A: ownership i = l + 64k; stages m=256 then m=64 (fwd) / reverse (inv)
__device__ __forceinline__ void phA_fwd(float2 A[16], const float2* W, int l){
    #pragma unroll
    for (int k0=0;k0<4;k0++){
        float2 w1=W[swz(l+64*k0)], w2=cmul(w1,w1), w3=cmul(w2,w1);
        bf_fwd(A[k0],A[k0+4],A[k0+8],A[k0+12],w1,w2,w3);
    }
    {   float2 w1=W[swz(4*l)], w2=cmul(w1,w1), w3=cmul(w2,w1);
        #pragma unroll
        for (int q=0;q<4;q++) bf_fwd(A[4*q],A[4*q+1],A[4*q+2],A[4*q+3],w1,w2,w3);
    }
}
__device__ __forceinline__ void phA_inv(float2 A[16], const float2* W, int l){
    {   float2 w1=W[swz(4*l)], w2=cmul(w1,w1), w3=cmul(w2,w1);
        #pragma unroll
        for (int q=0;q<4;q++) bf_inv(A[4*q],A[4*q+1],A[4*q+2],A[4*q+3],w1,w2,w3);
    }
    #pragma unroll
    for (int k0=0;k0<4;k0++){
        float2 w1=W[swz(l+64*k0)], w2=cmul(w1,w1), w3=cmul(w2,w1);
        bf_inv(A[k0],A[k0+4],A[k0+8],A[k0+12],w1,w2,w3);
    }
}
// Phase B: in-shared stage m=16. Thread (j=l&15, h=l>>4) owns
// {256h + 64qq + j + 16c} — exclusive set, one twiddle per thread.
__device__ __forceinline__ void phB_fwd(float2* sh, const float2* W, int l){
    int j = l & 15, h = l >> 4;
    float2 w1 = W[swz(16*j)], w2=cmul(w1,w1), w3=cmul(w2,w1);
    #pragma unroll
    for (int qq=0;qq<4;qq++){
        int i0 = 256*h + 64*qq + j;
        float2 a0=sh[swz(i0)], a1=sh[swz(i0+16)], a2=sh[swz(i0+32)], a3=sh[swz(i0+48)];
        bf_fwd(a0,a1,a2,a3,w1,w2,w3);
        sh[swz(i0)]=a0; sh[swz(i0+16)]=a1; sh[swz(i0+32)]=a2; sh[swz(i0+48)]=a3;
    }
}
__device__ __forceinline__ void phB_inv(float2* sh, const float2* W, int l){
    int j = l & 15, h = l >> 4;
    float2 w1 = W[swz(16*j)], w2=cmul(w1,w1), w3=cmul(w2,w1);
    #pragma unroll
    for (int qq=0;qq<4;qq++){
        int i0 = 256*h + 64*qq + j;
        float2 a0=sh[swz(i0)], a1=sh[swz(i0+16)], a2=sh[swz(i0+32)], a3=sh[swz(i0+48)];
        bf_inv(a0,a1,a2,a3,w1,w2,w3);
        sh[swz(i0)]=a0; sh[swz(i0+16)]=a1; sh[swz(i0+32)]=a2; sh[swz(i0+48)]=a3;
    }
}
// Phase C: ownership i = 16l + x (contiguous); stages m=4 then m=1 (fwd)
__device__ __forceinline__ void phC_fwd(float2 C[16], const float2* W){
    bf_fwd_nw(C[0],C[4],C[8],C[12]);
    #pragma unroll
    for (int j=1;j<4;j++){
        float2 w1=W[swz(64*j)], w2=cmul(w1,w1), w3=cmul(w2,w1);
        bf_fwd(C[j],C[j+4],C[j+8],C[j+12],w1,w2,w3);
    }
    #pragma unroll
    for (int p=0;p<4;p++) bf_fwd_nw(C[4*p],C[4*p+1],C[4*p+2],C[4*p+3]);
}
__device__ __forceinline__ void phC_inv(float2 C[16], const float2* W){
    #pragma unroll
    for (int p=0;p<4;p++) bf_inv_nw(C[4*p],C[4*p+1],C[4*p+2],C[4*p+3]);
    bf_inv_nw(C[0],C[4],C[8],C[12]);
    #pragma unroll
    for (int j=1;j<4;j++){
        float2 w1=W[swz(64*j)], w2=cmul(w1,w1), w3=cmul(w2,w1);
        bf_inv(C[j],C[j+4],C[j+8],C[j+12],w1,w2,w3);
    }
}

// -------------------- full row chains ---------------------------------------
// Storage permutation: logical freq pos i stored at P(i)=((i&15)<<6)|(i>>4).
// Phase-C global access (storage): addr = l + 64x  (coalesced).
// Phase-A global access (spatial, natural): addr = l + 64k (coalesced).

// freq storage -> spatial regs A (ownership l+64k)
__device__ __forceinline__ void row_ifft(const float2* __restrict__ Sin, size_t rowbase,
        float2* sh, const float2* W, int l, float2 A[16])
{
    #pragma unroll
    for (int x=0;x<16;x++) A[x] = Sin[rowbase + l + 64*x];
    phC_inv(A, W);
    #pragma unroll
    for (int x=0;x<16;x++) sh[swz(16*l + x)] = A[x];
    __syncthreads();
    phB_inv(sh, W, l);
    __syncthreads();
    #pragma unroll
    for (int k=0;k<16;k++) A[k] = sh[swz(l + 64*k)];
    phA_inv(A, W, l);
}
// spatial regs A -> freq storage
__device__ __forceinline__ void row_fft(float2* __restrict__ Sout, size_t rowbase,
        float2* sh, const float2* W, int l, float2 A[16])
{
    phA_fwd(A, W, l);
    #pragma unroll
    for (int k=0;k<16;k++) sh[swz(l + 64*k)] = A[k];
    __syncthreads();
    phB_fwd(sh, W, l);
    __syncthreads();
    #pragma unroll
    for (int x=0;x<16;x++) A[x] = sh[swz(16*l + x)];
    phC_fwd(A, W);
    #pragma unroll
    for (int x=0;x<16;x++) Sout[rowbase + l + 64*x] = A[x];
}

// -------------------- fused row kernels -------------------------------------
// 4 rows per block, 256 threads, row-private warps.
#define MID_MULT       1
#define MID_MULT_STORE 2
#define MID_RESID      3

template<int MID>
__global__ void __launch_bounds__(256) k_rowfused(const float2* __restrict__ in,
        float2* __restrict__ out, const float2* __restrict__ Tpl,
        float2* __restrict__ aux, const float* __restrict__ meas)
{
    __shared__ float2 sm[4*1024];
    __shared__ float2 W[256];
    int t = threadIdx.x;
    fill_tw(W, t);
    __syncthreads();
    int row = t >> 6, l = t & 63;
    size_t rowoff = ((size_t)blockIdx.x*4 + row) * 1024;
    float2* sh = sm + row*1024;
    float2 A[16];
    row_ifft(in, rowoff, sh, W, l, A);
    #pragma unroll
    for (int k=0;k<16;k++){
        size_t g = rowoff + l + 64*k;
        if (MID == MID_MULT){
            A[k] = cmul(A[k], Tpl[g]);
        } else if (MID == MID_MULT_STORE){
            A[k] = cmul(A[k], Tpl[g]);
            aux[g] = A[k];
        } else if (MID == MID_RESID){
            float a  = sqrtf(meas[g]);
            float mg = sqrtf(A[k].x*A[k].x + A[k].y*A[k].y);
            float f  = 1.0f - a/mg;
            A[k].x *= f; A[k].y *= f;
        }
    }
    row_fft(out, rowoff, sh, W, l, A);
}

// standalone forward: PRE 0 = spatial input, 2 = planewave * T
template<int PRE>
__global__ void __launch_bounds__(256) k_rowfwd(const float2* __restrict__ in,
        float2* __restrict__ out, const float2* __restrict__ Tpl,
        const float* __restrict__ na)
{
    __shared__ float2 sm[4*1024];
    __shared__ float2 W[256];
    int t = threadIdx.x;
    fill_tw(W, t);
    __syncthreads();
    int row = t >> 6, l = t & 63;
    int r = blockIdx.x*4 + row;
    size_t rowoff = (size_t)r * 1024;
    float2* sh = sm + row*1024;
    float t0 = 0.f, t1 = 0.f, yf = 0.f;
    if (PRE == 2){
        const float dfx = (float)(1.0/(0.325*1024.0));
        t0 = rintf((na[0]*2.0f)/dfx)*dfx;
        t1 = rintf((na[1]*2.0f)/dfx)*dfx;
        yf = (float)((double)(r - 512) * 0.325);
    }
    float2 A[16];
    #pragma unroll
    for (int k=0;k<16;k++){
        int idx = l + 64*k;
        size_t g = rowoff + idx;
        if (PRE == 2){
            float xf = (float)((double)(idx - 512) * 0.325);
            float ph = (float)(2.0*PI_D) * (t0*xf + t1*yf);
            float s, c; sincosf(ph, &s, &c);
            A[k] = cmul(make_float2(c, s), Tpl[g]);
        } else {
            A[k] = in[g];
        }
    }
    row_fft(out, rowoff, sh, W, l, A);
}

// merged backward: blocks [0,256) ubp chain, [256,512) u chain
template<int LAST>
__global__ void __launch_bounds__(256) k_rowback(float2* __restrict__ Sa,
        float2* __restrict__ Sb, const float2* __restrict__ Tz,
        const float2* __restrict__ Tzm1, const float2* __restrict__ Ur,
        float2* __restrict__ Uw, float2* __restrict__ Gout)
{
    __shared__ float2 sm[4*1024];
    __shared__ float2 W[256];
    int t = threadIdx.x;
    fill_tw(W, t);
    __syncthreads();
    int row = t >> 6, l = t & 63;
    bool isA = (blockIdx.x < 256);
    size_t rowoff = ((size_t)((isA ? blockIdx.x : blockIdx.x - 256)*4 + row)) * 1024;
    float2* S = isA ? Sa : Sb;
    float2* sh = sm + row*1024;
    float2 A[16];
    row_ifft(S, rowoff, sh, W, l, A);
    if (isA){
        #pragma unroll
        for (int k=0;k<16;k++){
            size_t g = rowoff + l + 64*k;
            float2 tv = Tz[g];
            float2 uu = Ur[g];
            float2 m1 = cmulc(A[k], uu);
            float2 m2 = cmulc(m1, tv);
            Gout[g] = make_float2(KAPF*m2.y, -KAPF*m2.x);
            A[k] = cmulc(A[k], tv);
        }
    } else {
        #pragma unroll
        for (int k=0;k<16;k++){
            size_t g = rowoff + l + 64*k;
            float2 tv = Tzm1[g];
            float inv = 1.0f/(tv.x*tv.x + tv.y*tv.y);
            float2 q  = cmulc(A[k], tv);
            A[k] = make_float2(q.x*inv, q.y*inv);
            Uw[g] = A[k];
        }
        if (LAST) return;
    }
    row_fft(S, rowoff, sh, W, l, A);
}

// final gradient g[0]
__global__ void __launch_bounds__(256) k_rowinv_grad(const float2* __restrict__ in,
        const float2* __restrict__ Uin, const float2* __restrict__ Tpl,
        float2* __restrict__ Gout)
{
    __shared__ float2 sm[4*1024];
    __shared__ float2 W[256];
    int t = threadIdx.x;
    fill_tw(W, t);
    __syncthreads();
    int row = t >> 6, l = t & 63;
    size_t rowoff = ((size_t)blockIdx.x*4 + row) * 1024;
    float2* sh = sm + row*1024;
    float2 A[16];
    row_ifft(in, rowoff, sh, W, l, A);
    #pragma unroll
    for (int k=0;k<16;k++){
        size_t g = rowoff + l + 64*k;
        float2 tv = Tpl[g];
        float2 uu = Uin[g];
        float2 m1 = cmulc(A[k], uu);
        float2 m2 = cmulc(m1, tv);
        Gout[g] = make_float2(KAPF*m2.y, -KAPF*m2.x);
    }
}

// -------------------- fused column pass -------------------------------------
// 4 storage-columns/block, 256 threads; FFT phases are column-private per warp.
#define CSTR 1026

__global__ void __launch_bounds__(256) k_colk(float2* __restrict__ da,
        float2* __restrict__ db, float phc, float scale)
{
    __shared__ float2 sm[4*CSTR];
    __shared__ float2 W[256];
    int t = threadIdx.x;
    fill_tw(W, t);
    int b = blockIdx.x;
    float2* d = da;
    if (b >= 256){ d = db; b -= 256; }
    int c0 = b * 4;
    // transpose-friendly load (natural p order into swizzled shared)
    #pragma unroll
    for (int i=0;i<16;i++){
        int l2 = t + i*256;
        int p = l2 >> 2, c = l2 & 3;
        sm[c*CSTR + swz(p)] = d[(size_t)p*1024 + c0 + c];
    }
    __syncthreads();
    int c = t >> 6, l = t & 63;
    float2* sh = sm + c*CSTR;
    float2 A[16];
    // forward
    #pragma unroll
    for (int k=0;k<16;k++) A[k] = sh[swz(l + 64*k)];
    phA_fwd(A, W, l);
    #pragma unroll
    for (int k=0;k<16;k++) sh[swz(l + 64*k)] = A[k];
    __syncthreads();
    phB_fwd(sh, W, l);
    __syncthreads();
    #pragma unroll
    for (int x=0;x<16;x++) A[x] = sh[swz(16*l + x)];
    phC_fwd(A, W);
    // analytic band-limited angular-spectrum kernel at digit-reversed freqs
    {
        const double R2LIM = ((0.65/0.5)*(0.65/0.5)) * ((0.325*1024.0)*(0.325*1024.0));
        const float  DFX2  = (float)(1.0/((0.325*1024.0)*(0.325*1024.0)));
        int sc = c0 + c;
        int lc = ((sc & 63) << 4) | (sc >> 6);   // P^{-1}: logical column
        int fx = fidx(rev4(lc));
        int fx2 = fx*fx;
        #pragma unroll
        for (int x=0;x<16;x++){
            int fy = fidx(rev4(16*l + x));
            int r2 = fx2 + fy*fy;
            if ((double)r2 < R2LIM){
                float kz = sqrtf(4.0f - (float)r2 * DFX2);
                float s, cc; sincosf(phc * kz, &s, &cc);
                A[x] = cmul(A[x], make_float2(cc*scale, s*scale));
            } else {
                A[x] = make_float2(0.f, 0.f);
            }
        }
    }
    // inverse
    phC_inv(A, W);
    #pragma unroll
    for (int x=0;x<16;x++) sh[swz(16*l + x)] = A[x];
    __syncthreads();
    phB_inv(sh, W, l);
    __syncthreads();
    #pragma unroll
    for (int k=0;k<16;k++) A[k] = sh[swz(l + 64*k)];
    phA_inv(A, W, l);
    #pragma unroll
    for (int k=0;k<16;k++) sh[swz(l + 64*k)] = A[k];
    __syncthreads();
    // transpose-friendly store
    #pragma unroll
    for (int i=0;i<16;i++){
        int l2 = t + i*256;
        int p = l2 >> 2, cc2 = l2 & 3;
        d[(size_t)p*1024 + c0 + cc2] = sm[cc2*CSTR + swz(p)];
    }
}

// -------------------- pointwise kernels -------------------------------------
__global__ void __launch_bounds__(256) k_T(const float* __restrict__ x, float2* __restrict__ T)
{
    int p = blockIdx.x*256 + threadIdx.x;
    float buf[32];
    float4* b4 = (float4*)buf;
    const float4* xb = (const float4*)(x + (size_t)p*32);
    #pragma unroll
    for (int i = 0; i < 8; i++) b4[i] = xb[i];
    #pragma unroll
    for (int zz = 0; zz < 16; zz++){
        float e = expf(-KAPF * buf[16 + zz]);
        float s, c; sincosf(KAPF * buf[zz], &s, &c);
        T[(size_t)zz*NPIX + p] = make_float2(e*c, e*s);
    }
}

__global__ void __launch_bounds__(256) k_out(const float* __restrict__ x,
        const float2* __restrict__ G, const float* __restrict__ alpha,
        float* __restrict__ out)
{
    int p = blockIdx.x*256 + threadIdx.x;
    float al = alpha[0];
    float buf[32];
    float4* b4 = (float4*)buf;
    const float4* xb = (const float4*)(x + (size_t)p*32);
    #pragma unroll
    for (int i = 0; i < 8; i++) b4[i] = xb[i];
    #pragma unroll
    for (int zz = 0; zz < 16; zz++){
        float2 g = G[(size_t)zz*NPIX + p];
        buf[zz]      -= al * g.x;
        buf[16 + zz] -= al * g.y;
    }
    float4* ob = (float4*)(out + (size_t)p*32);
    #pragma unroll
    for (int i = 0; i < 8; i++) ob[i] = b4[i];
}

// -------------------- launch ------------------------------------------------
extern "C" void kernel_launch(void* const* d_in, const int* in_sizes, int n_in,
                              void* d_out, int out_size)
{
    (void)in_sizes; (void)n_in; (void)out_size;
    const float* x     = (const float*)d_in[0];
    const float* meas  = (const float*)d_in[1];
    const float* na    = (const float*)d_in[2];
    const float* alpha = (const float*)d_in[3];
    float* out = (float*)d_out;

    float2 *T, *G, *Ua, *Ub, *Sa, *Sb;
    cudaGetSymbolAddress((void**)&T,  g_T);
    cudaGetSymbolAddress((void**)&G,  g_G);
    cudaGetSymbolAddress((void**)&Ua, g_Ua);
    cudaGetSymbolAddress((void**)&Ub, g_Ub);
    cudaGetSymbolAddress((void**)&Sa, g_Sa);
    cudaGetSymbolAddress((void**)&Sb, g_Sb);
    float2* Ubuf[2] = { Ua, Ub };

    const float SCALE  = 1.0f / 1048576.0f;             // ifft2 norm
    const float PHC_PK = (float)(2.0*PI_D * 3.25);      // 2*pi*DZ
    const float PHC_F  = (float)(2.0*PI_D * (-24.375)); // 2*pi*(-DZ*(NZ-1)/2)

    dim3 gr(256), gp(4096), gc1(256), gc2(512), gb(512);
    const int bt = 256;

    k_T<<<gp, bt>>>(x, T);

    // ---- forward multislice
    k_rowfwd<2><<<gr, bt>>>(nullptr, Sa, T, na);
    k_colk<<<gc1, bt>>>(Sa, nullptr, PHC_PK, SCALE);
    for (int zz = 1; zz <= 14; zz++){
        k_rowfused<MID_MULT><<<gr, bt>>>(Sa, Sa, T + (size_t)zz*NPIX, nullptr, nullptr);
        k_colk<<<gc1, bt>>>(Sa, nullptr, PHC_PK, SCALE);
    }
    // slice 15 multiply (store u@15 -> Ub), focus+pupil prop
    k_rowfused<MID_MULT_STORE><<<gr, bt>>>(Sa, Sa, T + (size_t)15*NPIX, Ub, nullptr);
    k_colk<<<gc1, bt>>>(Sa, nullptr, PHC_F, SCALE);
    // residual + backprop through conj(pupil*focus)
    k_rowfused<MID_RESID><<<gr, bt>>>(Sa, Sa, nullptr, nullptr, meas);
    k_colk<<<gc1, bt>>>(Sa, nullptr, -PHC_F, SCALE);

    // ---- start u backward chain
    k_rowfwd<0><<<gr, bt>>>(Ub, Sb, nullptr, nullptr);
    k_colk<<<gc1, bt>>>(Sb, nullptr, -PHC_PK, SCALE);

    // ---- merged backward loop: zz = 15..2
    for (int zz = 15; zz >= 2; zz--){
        k_rowback<0><<<gb, bt>>>(Sa, Sb, T + (size_t)zz*NPIX, T + (size_t)(zz-1)*NPIX,
                                 Ubuf[zz & 1], Ubuf[(zz-1) & 1], G + (size_t)zz*NPIX);
        k_colk<<<gc2, bt>>>(Sa, Sb, -PHC_PK, SCALE);
    }
    // zz = 1: grad + final u division (u@0), ubp propagates once more
    k_rowback<1><<<gb, bt>>>(Sa, Sb, T + (size_t)NPIX, T,
                             Ubuf[1], Ubuf[0], G + (size_t)NPIX);
    k_colk<<<gc1, bt>>>(Sa, nullptr, -PHC_PK, SCALE);
    k_rowinv_grad<<<gr, bt>>>(Sa, Ubuf[0], T, G);

    k_out<<<gp, bt>>>(x, G, alpha, out);
}

// round 17
// speedup vs baseline: 1.3490x; 1.3490x over previous
#include <cuda_runtime.h>

// ---------------------------------------------------------------------------
// Multislice gradient step — custom radix-4 FFT (digit-reversed, no reorder),
// XOR bank swizzle, register boundary stages, 256-entry shared twiddles,
// 4-col column blocks, merged backward-chain launches, register prefetch of
// mid-phase operands, shared-staged pointwise kernels.
// ---------------------------------------------------------------------------

#define NPIX (1024*1024)
#define NZS  16
#define PI_D 3.14159265358979323846
#define KAPF ((float)(2.0*PI_D*6.5))

// -------------------- device scratch ---------------------------------------
__device__ float2 g_T [(size_t)NZS*NPIX];   // transmittance planes
__device__ float2 g_G [(size_t)NZS*NPIX];   // gradient planes
__device__ float2 g_Ua[NPIX];               // u ping-pong A
__device__ float2 g_Ub[NPIX];               // u ping-pong B
__device__ float2 g_Sa[NPIX];               // freq scratch (ubp / fwd chain)
__device__ float2 g_Sb[NPIX];               // freq scratch (u chain)

// -------------------- complex helpers --------------------------------------
__device__ __forceinline__ float2 cadd(float2 a, float2 b){ return make_float2(a.x+b.x, a.y+b.y); }
__device__ __forceinline__ float2 csub(float2 a, float2 b){ return make_float2(a.x-b.x, a.y-b.y); }
__device__ __forceinline__ float2 cmul(float2 a, float2 b){ return make_float2(a.x*b.x-a.y*b.y, a.x*b.y+a.y*b.x); }
__device__ __forceinline__ float2 cmulc(float2 a, float2 b){ return make_float2(a.x*b.x+a.y*b.y, a.y*b.x-a.x*b.y); }

// bank swizzle: conflict-free for all stride patterns used
__device__ __forceinline__ int swz(int a){ return a ^ ((5*(a>>4)) & 15); }

__device__ __forceinline__ int rev4(int v){
    return ((v & 3) << 8) | (((v >> 2) & 3) << 6) | (((v >> 4) & 3) << 4)
         | (((v >> 6) & 3) << 2) | ((v >> 8) & 3);
}
__device__ __forceinline__ int fidx(int k){ return (k < 512) ? k : k - 1024; }

// 256-entry twiddle table: exp(-2*pi*i*k/1024), k<256 (w2,w3 derived by mult)
__device__ __forceinline__ void fill_tw(float2* W, int tid){
    float s, c;
    sincospif(-(float)tid * (1.0f/512.0f), &s, &c);
    W[swz(tid)] = make_float2(c, s);
}

// -------------------- shared-memory radix-4 stages --------------------------
__device__ __forceinline__ void st_fwd(float2* d, const float2* W, int t, int m){
    int j  = t & (m - 1);
    int i0 = ((t - j) << 2) + j;
    float2 a0 = d[swz(i0)], a1 = d[swz(i0+m)], a2 = d[swz(i0+2*m)], a3 = d[swz(i0+3*m)];
    float2 t0 = cadd(a0,a2), t1 = csub(a0,a2);
    float2 t2 = cadd(a1,a3), u  = csub(a1,a3);
    float2 mi = make_float2(u.y, -u.x);
    float2 w1 = W[swz(j * (256/m))];
    float2 w2 = cmul(w1,w1), w3 = cmul(w2,w1);
    d[swz(i0)]     = cadd(t0,t2);
    d[swz(i0+m)]   = cmul(cadd(t1,mi), w1);
    d[swz(i0+2*m)] = cmul(csub(t0,t2), w2);
    d[swz(i0+3*m)] = cmul(csub(t1,mi), w3);
}
__device__ __forceinline__ void st_inv(float2* d, const float2* W, int t, int m){
    int j  = t & (m - 1);
    int i0 = ((t - j) << 2) + j;
    float2 w1 = W[swz(j * (256/m))];
    float2 w2 = cmul(w1,w1), w3 = cmul(w2,w1);
    float2 c0 = d[swz(i0)];
    float2 c1 = cmulc(d[swz(i0+m)],   w1);
    float2 c2 = cmulc(d[swz(i0+2*m)], w2);
    float2 c3 = cmulc(d[swz(i0+3*m)], w3);
    float2 t0 = cadd(c0,c2), t1 = csub(c0,c2);
    float2 t2 = cadd(c1,c3), u  = csub(c1,c3);
    float2 pi = make_float2(-u.y, u.x);
    d[swz(i0)]     = cadd(t0,t2);
    d[swz(i0+m)]   = cadd(t1,pi);
    d[swz(i0+2*m)] = csub(t0,t2);
    d[swz(i0+3*m)] = csub(t1,pi);
}

// -------------------- register boundary stages ------------------------------
__device__ __forceinline__ void st256_fwd_reg(float2* d, const float2* W, int t, const float2 v[4]){
    float2 t0 = cadd(v[0],v[2]), t1 = csub(v[0],v[2]);
    float2 t2 = cadd(v[1],v[3]), u  = csub(v[1],v[3]);
    float2 mi = make_float2(u.y, -u.x);
    float2 w1 = W[swz(t)];
    float2 w2 = cmul(w1,w1), w3 = cmul(w2,w1);
    d[swz(t)]     = cadd(t0,t2);
    d[swz(t+256)] = cmul(cadd(t1,mi), w1);
    d[swz(t+512)] = cmul(csub(t0,t2), w2);
    d[swz(t+768)] = cmul(csub(t1,mi), w3);
}
__device__ __forceinline__ void st1_fwd_reg(const float2* d, int t, float2 r[4]){
    int i0 = 4*t;
    float2 a0 = d[swz(i0)], a1 = d[swz(i0+1)], a2 = d[swz(i0+2)], a3 = d[swz(i0+3)];
    float2 t0 = cadd(a0,a2), t1 = csub(a0,a2);
    float2 t2 = cadd(a1,a3), u  = csub(a1,a3);
    float2 mi = make_float2(u.y, -u.x);
    r[0] = cadd(t0,t2); r[1] = cadd(t1,mi); r[2] = csub(t0,t2); r[3] = csub(t1,mi);
}
__device__ __forceinline__ void st1_inv_reg(float2* d, int t, const float2 r[4]){
    float2 t0 = cadd(r[0],r[2]), t1 = csub(r[0],r[2]);
    float2 t2 = cadd(r[1],r[3]), u  = csub(r[1],r[3]);
    float2 pi = make_float2(-u.y, u.x);
    int i0 = 4*t;
    d[swz(i0)]   = cadd(t0,t2);
    d[swz(i0+1)] = cadd(t1,pi);
    d[swz(i0+2)] = csub(t0,t2);
    d[swz(i0+3)] = csub(t1,pi);
}
__device__ __forceinline__ void st256_inv_reg(const float2* d, const float2* W, int t, float2 v[4]){
    float2 w1 = W[swz(t)];
    float2 w2 = cmul(w1,w1), w3 = cmul(w2,w1);
    float2 c0 = d[swz(t)];
    float2 c1 = cmulc(d[swz(t+256)], w1);
    float2 c2 = cmulc(d[swz(t+512)], w2);
    float2 c3 = cmulc(d[swz(t+768)], w3);
    float2 t0 = cadd(c0,c2), t1 = csub(c0,c2);
    float2 t2 = cadd(c1,c3), u  = csub(c1,c3);
    float2 pi = make_float2(-u.y, u.x);
    v[0] = cadd(t0,t2); v[1] = cadd(t1,pi); v[2] = csub(t0,t2); v[3] = csub(t1,pi);
}

// inverse-row chain from PRELOADED registers r[4] -> spatial v[4]
__device__ __forceinline__ void row_inverse_pre(float2 r[4],
        float2* sd, const float2* sw, int t, float2 v[4])
{
    st1_inv_reg(sd, t, r);
    __syncthreads();
    st_inv(sd, sw, t, 4);  __syncthreads();
    st_inv(sd, sw, t, 16); __syncthreads();
    st_inv(sd, sw, t, 64); __syncthreads();
    st256_inv_reg(sd, sw, t, v);
}
// forward-row chain: spatial v[4] -> global
__device__ __forceinline__ void row_forward(float2* __restrict__ out, size_t rowoff,
                                            float2* sd, const float2* sw, int t, const float2 v[4])
{
    st256_fwd_reg(sd, sw, t, v);
    __syncthreads();
    st_fwd(sd, sw, t, 64); __syncthreads();
    st_fwd(sd, sw, t, 16); __syncthreads();
    st_fwd(sd, sw, t, 4);  __syncthreads();
    float2 r[4];
    st1_fwd_reg(sd, t, r);
    float4* og = (float4*)(out + rowoff + 4*t);
    og[0] = make_float4(r[0].x,r[0].y,r[1].x,r[1].y);
    og[1] = make_float4(r[2].x,r[2].y,r[3].x,r[3].y);
}

__device__ __forceinline__ void load_freq(const float2* __restrict__ in, size_t rowoff,
                                          int t, float2 r[4])
{
    const float4* ing = (const float4*)(in + rowoff + 4*t);
    float4 p0 = ing[0], p1 = ing[1];
    r[0] = make_float2(p0.x,p0.y); r[1] = make_float2(p0.z,p0.w);
    r[2] = make_float2(p1.x,p1.y); r[3] = make_float2(p1.z,p1.w);
}

// -------------------- fused row kernels (forward loop) ----------------------
#define MID_MULT       1
#define MID_MULT_STORE 2
#define MID_RESID      3

template<int MID>
__global__ void __launch_bounds__(256) k_rowfused(const float2* __restrict__ in,
        float2* __restrict__ out, const float2* __restrict__ Tpl,
        float2* __restrict__ aux, const float* __restrict__ meas)
{
    __shared__ float2 sd[1024];
    __shared__ float2 sw[256];
    int t = threadIdx.x;
    size_t rowoff = (size_t)blockIdx.x * 1024;
    fill_tw(sw, t);
    // preload FFT input + mid-phase operands (hide DRAM latency under FFT)
    float2 r[4];
    load_freq(in, rowoff, t, r);
    float2 Tv[4]; float mv[4];
    #pragma unroll
    for (int i = 0; i < 4; i++){
        size_t g = rowoff + t + 256*i;
        if (MID == MID_MULT || MID == MID_MULT_STORE) Tv[i] = Tpl[g];
        if (MID == MID_RESID) mv[i] = meas[g];
    }
    float2 v[4];
    row_inverse_pre(r, sd, sw, t, v);
    #pragma unroll
    for (int i = 0; i < 4; i++){
        size_t g = rowoff + t + 256*i;
        if (MID == MID_MULT){
            v[i] = cmul(v[i], Tv[i]);
        } else if (MID == MID_MULT_STORE){
            v[i] = cmul(v[i], Tv[i]);
            aux[g] = v[i];
        } else if (MID == MID_RESID){
            float a  = sqrtf(mv[i]);
            float mg = sqrtf(v[i].x*v[i].x + v[i].y*v[i].y);
            float f  = 1.0f - a/mg;
            v[i].x *= f; v[i].y *= f;
        }
    }
    __syncthreads();
    row_forward(out, rowoff, sd, sw, t, v);
}

// standalone forward: PRE 0 = plain spatial input, 2 = planewave * T
template<int PRE>
__global__ void __launch_bounds__(256) k_rowfwd(const float2* __restrict__ in,
        float2* __restrict__ out, const float2* __restrict__ Tpl,
        const float* __restrict__ na)
{
    __shared__ float2 sd[1024];
    __shared__ float2 sw[256];
    int t = threadIdx.x;
    int r = blockIdx.x;
    size_t rowoff = (size_t)r * 1024;
    fill_tw(sw, t);
    float t0 = 0.f, t1 = 0.f, yf = 0.f;
    if (PRE == 2){
        const float dfx = (float)(1.0/(0.325*1024.0));
        t0 = rintf((na[0]*2.0f)/dfx)*dfx;
        t1 = rintf((na[1]*2.0f)/dfx)*dfx;
        yf = (float)((double)(r - 512) * 0.325);
    }
    float2 v[4];
    #pragma unroll
    for (int i = 0; i < 4; i++){
        int cidx = t + 256*i;
        size_t g = rowoff + cidx;
        if (PRE == 2){
            float xf = (float)((double)(cidx - 512) * 0.325);
            float ph = (float)(2.0*PI_D) * (t0*xf + t1*yf);
            float s, c; sincosf(ph, &s, &c);
            v[i] = cmul(make_float2(c, s), Tpl[g]);
        } else {
            v[i] = in[g];
        }
    }
    row_forward(out, rowoff, sd, sw, t, v);
}

// -------------------- merged backward row kernel ----------------------------
// blocks [0,1024): ubp chain — inverse, grad write, *conj(T[zz]), forward
// blocks [1024,2048): u chain — inverse, /T[zz-1], store Uw, forward (unless LAST)
template<int LAST>
__global__ void __launch_bounds__(256) k_rowback(float2* __restrict__ Sa,
        float2* __restrict__ Sb, const float2* __restrict__ Tz,
        const float2* __restrict__ Tzm1, const float2* __restrict__ Ur,
        float2* __restrict__ Uw, float2* __restrict__ Gout)
{
    __shared__ float2 sd[1024];
    __shared__ float2 sw[256];
    int t = threadIdx.x;
    fill_tw(sw, t);
    bool isA = (blockIdx.x < 1024);
    size_t rowoff = (size_t)(isA ? blockIdx.x : blockIdx.x - 1024) * 1024;
    float2* S = isA ? Sa : Sb;
    // preload FFT input + T (and U) operands
    float2 r[4];
    load_freq(S, rowoff, t, r);
    float2 Tv[4], Uv[4];
    #pragma unroll
    for (int i = 0; i < 4; i++){
        size_t g = rowoff + t + 256*i;
        if (isA){ Tv[i] = Tz[g]; Uv[i] = Ur[g]; }
        else    { Tv[i] = Tzm1[g]; }
    }
    float2 v[4];
    row_inverse_pre(r, sd, sw, t, v);
    if (isA){
        #pragma unroll
        for (int i = 0; i < 4; i++){
            size_t g = rowoff + t + 256*i;
            float2 m1 = cmulc(v[i], Uv[i]);
            float2 m2 = cmulc(m1, Tv[i]);
            Gout[g] = make_float2(KAPF*m2.y, -KAPF*m2.x);
            v[i] = cmulc(v[i], Tv[i]);
        }
    } else {
        #pragma unroll
        for (int i = 0; i < 4; i++){
            size_t g = rowoff + t + 256*i;
            float inv = 1.0f/(Tv[i].x*Tv[i].x + Tv[i].y*Tv[i].y);
            float2 q  = cmulc(v[i], Tv[i]);
            v[i] = make_float2(q.x*inv, q.y*inv);
            Uw[g] = v[i];
        }
        if (LAST) return;   // u chain ends at slice 0
    }
    __syncthreads();
    row_forward(S, rowoff, sd, sw, t, v);
}

// final gradient g[0]
__global__ void __launch_bounds__(256) k_rowinv_grad(const float2* __restrict__ in,
        const float2* __restrict__ Uin, const float2* __restrict__ Tpl,
        float2* __restrict__ Gout)
{
    __shared__ float2 sd[1024];
    __shared__ float2 sw[256];
    int t = threadIdx.x;
    size_t rowoff = (size_t)blockIdx.x * 1024;
    fill_tw(sw, t);
    float2 r[4];
    load_freq(in, rowoff, t, r);
    float2 Tv[4], Uv[4];
    #pragma unroll
    for (int i = 0; i < 4; i++){
        size_t g = rowoff + t + 256*i;
        Tv[i] = Tpl[g]; Uv[i] = Uin[g];
    }
    float2 v[4];
    row_inverse_pre(r, sd, sw, t, v);
    #pragma unroll
    for (int i = 0; i < 4; i++){
        size_t g = rowoff + t + 256*i;
        float2 m1 = cmulc(v[i], Uv[i]);
        float2 m2 = cmulc(m1, Tv[i]);
        Gout[g] = make_float2(KAPF*m2.y, -KAPF*m2.x);
    }
}

// -------------------- fused column pass -------------------------------------
// 4 columns/block, 256 threads. colDIF -> analytic kernel at digit-reversed
// freqs -> colDIT, in-place. Blocks >= 256 work on db (merged backward pairs).
#define CSTR 1026

__global__ void __launch_bounds__(256) k_colk(float2* __restrict__ da,
        float2* __restrict__ db, float phc, float scale)
{
    __shared__ float2 sm[4*CSTR];
    __shared__ float2 sw[256];
    int t = threadIdx.x;
    int b = blockIdx.x;
    float2* d = da;
    if (b >= 256){ d = db; b -= 256; }
    int c0 = b * 4;
    fill_tw(sw, t);
    #pragma unroll
    for (int i = 0; i < 16; i++){
        int l = t + i*256;
        int p = l >> 2, c = l & 3;
        sm[c*CSTR + swz(p)] = d[(size_t)p*1024 + c0 + c];
    }
    __syncthreads();
    #pragma unroll
    for (int m = 256; m >= 4; m >>= 2){
        #pragma unroll
        for (int c = 0; c < 4; c++) st_fwd(sm + c*CSTR, sw, t, m);
        __syncthreads();
    }
    // fused m=1 fwd + analytic kernel multiply + m=1 inv (registers)
    const double R2LIM = ((0.65/0.5)*(0.65/0.5)) * ((0.325*1024.0)*(0.325*1024.0));
    const float  DFX2  = (float)(1.0/((0.325*1024.0)*(0.325*1024.0)));
    int fy[4];
    #pragma unroll
    for (int k = 0; k < 4; k++) fy[k] = fidx(rev4(4*t + k));
    #pragma unroll
    for (int c = 0; c < 4; c++){
        float2* dc = sm + c*CSTR;
        float2 rr[4];
        st1_fwd_reg(dc, t, rr);
        int fxv = fidx(rev4(c0 + c));
        int fx2 = fxv*fxv;
        #pragma unroll
        for (int k = 0; k < 4; k++){
            int r2 = fx2 + fy[k]*fy[k];
            if ((double)r2 < R2LIM){
                float kz = sqrtf(4.0f - (float)r2 * DFX2);
                float s, cx; sincosf(phc * kz, &s, &cx);
                rr[k] = cmul(rr[k], make_float2(cx*scale, s*scale));
            } else {
                rr[k] = make_float2(0.f, 0.f);
            }
        }
        st1_inv_reg(dc, t, rr);
    }
    __syncthreads();
    #pragma unroll
    for (int m = 4; m <= 256; m <<= 2){
        #pragma unroll
        for (int c = 0; c < 4; c++) st_inv(sm + c*CSTR, sw, t, m);
        __syncthreads();
    }
    #pragma unroll
    for (int i = 0; i < 16; i++){
        int l = t + i*256;
        int p = l >> 2, c = l & 3;
        d[(size_t)p*1024 + c0 + c] = sm[c*CSTR + swz(p)];
    }
}

// -------------------- pointwise kernels (shared-staged, coalesced) ----------
__global__ void __launch_bounds__(256) k_T(const float* __restrict__ x,
                                           float2* __restrict__ T)
{
    __shared__ float xs[256*33];
    int t = threadIdx.x;
    size_t base = (size_t)blockIdx.x * 8192;          // floats per block
    const float4* xg = (const float4*)(x + base);
    #pragma unroll
    for (int i = 0; i < 8; i++){
        int f4 = t + i*256;
        float4 vv = xg[f4];
        float* dst = &xs[(f4 >> 3)*33 + (f4 & 7)*4];
        dst[0]=vv.x; dst[1]=vv.y; dst[2]=vv.z; dst[3]=vv.w;
    }
    __syncthreads();
    int p = blockIdx.x*256 + t;
    const float* m = &xs[t*33];
    #pragma unroll
    for (int zz = 0; zz < 16; zz++){
        float e = expf(-KAPF * m[16 + zz]);
        float s, c; sincosf(KAPF * m[zz], &s, &c);
        T[(size_t)zz*NPIX + p] = make_float2(e*c, e*s);
    }
}

__global__ void __launch_bounds__(256) k_out(const float* __restrict__ x,
        const float2* __restrict__ G, const float* __restrict__ alpha,
        float* __restrict__ out)
{
    __shared__ float xs[256*33];
    int t = threadIdx.x;
    size_t base = (size_t)blockIdx.x * 8192;
    const float4* xg = (const float4*)(x + base);
    #pragma unroll
    for (int i = 0; i < 8; i++){
        int f4 = t + i*256;
        float4 vv = xg[f4];
        float* dst = &xs[(f4 >> 3)*33 + (f4 & 7)*4];
        dst[0]=vv.x; dst[1]=vv.y; dst[2]=vv.z; dst[3]=vv.w;
    }
    __syncthreads();
    float al = alpha[0];
    int p = blockIdx.x*256 + t;
    float* m = &xs[t*33];
    #pragma unroll
    for (int zz = 0; zz < 16; zz++){
        float2 g = G[(size_t)zz*NPIX + p];
        m[zz]      -= al * g.x;
        m[16 + zz] -= al * g.y;
    }
    __syncthreads();
    float4* og = (float4*)(out + base);
    #pragma unroll
    for (int i = 0; i < 8; i++){
        int f4 = t + i*256;
        const float* src = &xs[(f4 >> 3)*33 + (f4 & 7)*4];
        og[f4] = make_float4(src[0], src[1], src[2], src[3]);
    }
}

// -------------------- launch ------------------------------------------------
extern "C" void kernel_launch(void* const* d_in, const int* in_sizes, int n_in,
                              void* d_out, int out_size)
{
    (void)in_sizes; (void)n_in; (void)out_size;
    const float* x     = (const float*)d_in[0];
    const float* meas  = (const float*)d_in[1];
    const float* na    = (const float*)d_in[2];
    const float* alpha = (const float*)d_in[3];
    float* out = (float*)d_out;

    float2 *T, *G, *Ua, *Ub, *Sa, *Sb;
    cudaGetSymbolAddress((void**)&T,  g_T);
    cudaGetSymbolAddress((void**)&G,  g_G);
    cudaGetSymbolAddress((void**)&Ua, g_Ua);
    cudaGetSymbolAddress((void**)&Ub, g_Ub);
    cudaGetSymbolAddress((void**)&Sa, g_Sa);
    cudaGetSymbolAddress((void**)&Sb, g_Sb);
    float2* Ubuf[2] = { Ua, Ub };

    const float SCALE  = 1.0f / 1048576.0f;             // ifft2 norm
    const float PHC_PK = (float)(2.0*PI_D * 3.25);      // 2*pi*DZ
    const float PHC_F  = (float)(2.0*PI_D * (-24.375)); // 2*pi*(-DZ*(NZ-1)/2)

    dim3 gr(1024), gp(4096), gc1(256), gc2(512), gb(2048);
    const int bt = 256;

    k_T<<<gp, bt>>>(x, T);

    // ---- forward multislice
    k_rowfwd<2><<<gr, bt>>>(nullptr, Sa, T, na);
    k_colk<<<gc1, bt>>>(Sa, nullptr, PHC_PK, SCALE);
    for (int zz = 1; zz <= 14; zz++){
        k_rowfused<MID_MULT><<<gr, bt>>>(Sa, Sa, T + (size_t)zz*NPIX, nullptr, nullptr);
        k_colk<<<gc1, bt>>>(Sa, nullptr, PHC_PK, SCALE);
    }
    // slice 15 multiply (store u@15 -> Ub), focus+pupil prop
    k_rowfused<MID_MULT_STORE><<<gr, bt>>>(Sa, Sa, T + (size_t)15*NPIX, Ub, nullptr);
    k_colk<<<gc1, bt>>>(Sa, nullptr, PHC_F, SCALE);
    // residual + backprop through conj(pupil*focus)
    k_rowfused<MID_RESID><<<gr, bt>>>(Sa, Sa, nullptr, nullptr, meas);
    k_colk<<<gc1, bt>>>(Sa, nullptr, -PHC_F, SCALE);

    // ---- start u backward chain
    k_rowfwd<0><<<gr, bt>>>(Ub, Sb, nullptr, nullptr);
    k_colk<<<gc1, bt>>>(Sb, nullptr, -PHC_PK, SCALE);

    // ---- merged backward loop: zz = 15..2
    for (int zz = 15; zz >= 2; zz--){
        k_rowback<0><<<gb, bt>>>(Sa, Sb, T + (size_t)zz*NPIX, T + (size_t)(zz-1)*NPIX,
                                 Ubuf[zz & 1], Ubuf[(zz-1) & 1], G + (size_t)zz*NPIX);
        k_colk<<<gc2, bt>>>(Sa, Sb, -PHC_PK, SCALE);
    }
    // zz = 1: grad + final u division (u@0), ubp propagates once more
    k_rowback<1><<<gb, bt>>>(Sa, Sb, T + (size_t)NPIX, T,
                             Ubuf[1], Ubuf[0], G + (size_t)NPIX);
    k_colk<<<gc1, bt>>>(Sa, nullptr, -PHC_PK, SCALE);
    k_rowinv_grad<<<gr, bt>>>(Sa, Ubuf[0], T, G);

    k_out<<<gp, bt>>>(x, G, alpha, out);
}